// round 1
// baseline (speedup 1.0000x reference)
#include <cuda_runtime.h>
#include <math.h>
#include <stdint.h>

// Problem constants (fixed by reference setup_inputs)
#define NN 8192
#define DD 256
#define GG 2048          // NN / PIC_NUM
#define NTILE 128        // number of 64-wide column tiles
#define TPAR 0.04f
// exp(dot/T) = 2^(dot * log2(e)/T)
#define SCALE 36.067376022224085f

// Scratch (static __device__ arrays — no allocation in kernel_launch)
__device__ float g_partial[NN * NTILE];   // [row][coltile] masked exp-rowsum partials (4 MB)
__device__ float g_group_loss[GG];

__device__ __forceinline__ float ex2f_(float v) {
    float r;
    asm("ex2.approx.f32 %0, %1;" : "=f"(r) : "f"(v));
    return r;
}

// ---------------------------------------------------------------------------
// Kernel 1: Gram tile (64x64), K-chunk 32, fused exp + in-group mask + row sum
// Thread (tx,ty) of 16x16 handles rows R0+ty+{0,16,32,48}, cols C0+tx+{0,16,32,48}
// ---------------------------------------------------------------------------
#define BM 64
#define BN 64
#define BK 32

__global__ __launch_bounds__(256) void gram_kernel(const float* __restrict__ x) {
    __shared__ float As[BK][BM + 1];   // +1 pad: conflict-free transposed stores
    __shared__ float Bs[BK][BN + 1];

    const int bi = blockIdx.y, bj = blockIdx.x;
    const int R0 = bi * BM, C0 = bj * BN;
    const int tid = threadIdx.x;
    const int tx = tid & 15, ty = tid >> 4;

    float acc[4][4];
    #pragma unroll
    for (int i = 0; i < 4; i++)
        #pragma unroll
        for (int j = 0; j < 4; j++) acc[i][j] = 0.f;

    for (int kk = 0; kk < DD; kk += BK) {
        // Load 64x32 A and B tiles (512 float4 each; 2 per thread), transpose to [k][row]
        #pragma unroll
        for (int u = 0; u < 2; u++) {
            const int idx = tid + u * 256;
            const int r  = idx >> 3;          // 0..63
            const int c4 = (idx & 7) << 2;    // 0,4,...,28
            float4 va = *reinterpret_cast<const float4*>(x + (R0 + r) * DD + kk + c4);
            As[c4 + 0][r] = va.x; As[c4 + 1][r] = va.y;
            As[c4 + 2][r] = va.z; As[c4 + 3][r] = va.w;
            float4 vb = *reinterpret_cast<const float4*>(x + (C0 + r) * DD + kk + c4);
            Bs[c4 + 0][r] = vb.x; Bs[c4 + 1][r] = vb.y;
            Bs[c4 + 2][r] = vb.z; Bs[c4 + 3][r] = vb.w;
        }
        __syncthreads();

        #pragma unroll
        for (int k = 0; k < BK; k++) {
            float a0 = As[k][ty     ], a1 = As[k][ty + 16],
                  a2 = As[k][ty + 32], a3 = As[k][ty + 48];
            float b0 = Bs[k][tx     ], b1 = Bs[k][tx + 16],
                  b2 = Bs[k][tx + 32], b3 = Bs[k][tx + 48];
            acc[0][0] += a0 * b0; acc[0][1] += a0 * b1; acc[0][2] += a0 * b2; acc[0][3] += a0 * b3;
            acc[1][0] += a1 * b0; acc[1][1] += a1 * b1; acc[1][2] += a1 * b2; acc[1][3] += a1 * b3;
            acc[2][0] += a2 * b0; acc[2][1] += a2 * b1; acc[2][2] += a2 * b2; acc[2][3] += a2 * b3;
            acc[3][0] += a3 * b0; acc[3][1] += a3 * b1; acc[3][2] += a3 * b2; acc[3][3] += a3 * b3;
        }
        __syncthreads();
    }

    // Epilogue: exp(dot/T), zero out in-group (same 4-group) entries, row-partials
    float rowp[4];
    #pragma unroll
    for (int i = 0; i < 4; i++) {
        const int r = R0 + ty + 16 * i;
        float s = 0.f;
        #pragma unroll
        for (int j = 0; j < 4; j++) {
            const int c = C0 + tx + 16 * j;
            float e = ex2f_(acc[i][j] * SCALE);
            if ((r >> 2) == (c >> 2)) e = 0.f;   // mask own group's columns
            s += e;
        }
        rowp[i] = s;
    }
    // Reduce across the 16 tx lanes (warp = two ty rows of 16 tx lanes)
    #pragma unroll
    for (int m = 1; m <= 8; m <<= 1) {
        #pragma unroll
        for (int i = 0; i < 4; i++)
            rowp[i] += __shfl_xor_sync(0xffffffffu, rowp[i], m);
    }
    if (tx == 0) {
        #pragma unroll
        for (int i = 0; i < 4; i++)
            g_partial[(R0 + ty + 16 * i) * NTILE + bj] = rowp[i];
    }
}

// ---------------------------------------------------------------------------
// Kernel 2: one warp per group. 4x4 P block stats + neg from partials + softplus
// ---------------------------------------------------------------------------
__global__ __launch_bounds__(256) void group_kernel(const float* __restrict__ x) {
    const int warp = threadIdx.x >> 5;
    const int lane = threadIdx.x & 31;
    const int g = blockIdx.x * 8 + warp;   // grid = 256 blocks * 8 warps = 2048 exact

    // Each of 16 pairs (i,j) computed by 2 lanes (128-dim halves)
    const int pair = lane & 15;
    const int half = lane >> 4;
    const int i = pair >> 2, j = pair & 3;
    const float* xi = x + (4 * g + i) * DD + half * 128;
    const float* xj = x + (4 * g + j) * DD + half * 128;
    float dot = 0.f;
    #pragma unroll
    for (int k = 0; k < 128; k += 4) {
        float4 a = *reinterpret_cast<const float4*>(xi + k);
        float4 b = *reinterpret_cast<const float4*>(xj + k);
        dot += a.x * b.x + a.y * b.y + a.z * b.z + a.w * b.w;
    }
    dot += __shfl_down_sync(0xffffffffu, dot, 16);   // lanes 0..15 hold full dot

    // exp(-s) with s = dot/T   (range safe in fp32: |s| <= ~25)
    float en = ex2f_(-dot * SCALE);

    // row sums over j within 4-lane groups
    float rowsum = en;
    rowsum += __shfl_xor_sync(0xffffffffu, rowsum, 1);
    rowsum += __shfl_xor_sync(0xffffffffu, rowsum, 2);
    float inv = 0.25f / rowsum;   // each row replicated on 4 lanes -> weight 1/4

    // reduce over the 16 pair-lanes
    float sum_en = en, sum_inv = inv;
    #pragma unroll
    for (int m = 1; m < 16; m <<= 1) {
        sum_en  += __shfl_xor_sync(0xffffffffu, sum_en,  m, 16);
        sum_inv += __shfl_xor_sync(0xffffffffu, sum_inv, m, 16);
    }

    // neg: sum the 4 rows' masked exp-rowsum partials (4 * 128 = 512 values)
    float S = 0.f;
    const float* part = g_partial + (size_t)(4 * g) * NTILE;
    #pragma unroll
    for (int t = 0; t < 512; t += 32) S += part[t + lane];
    #pragma unroll
    for (int m = 1; m < 32; m <<= 1) S += __shfl_xor_sync(0xffffffffu, S, m);

    if (lane == 0) {
        float hard_pos  = -TPAR * logf(sum_en);
        float least_pos =  TPAR * logf(sum_inv);
        float neg       =  TPAR * logf(S);
        float alpha = (hard_pos >= 0.f)
            ? (2.f * least_pos * hard_pos / (hard_pos + least_pos)) : 0.f;
        float margin = alpha * hard_pos + (1.f - alpha) * least_pos;
        float z = (neg - margin) / TPAR;
        float sp = (z > 0.f) ? (z + log1pf(expf(-z))) : log1pf(expf(z));
        g_group_loss[g] = sp;
    }
}

// ---------------------------------------------------------------------------
// Kernel 3: deterministic mean of 2048 group losses
// ---------------------------------------------------------------------------
__global__ void reduce_kernel(float* __restrict__ out) {
    __shared__ float sm[256];
    const int t = threadIdx.x;
    float s = 0.f;
    for (int idx = t; idx < GG; idx += 256) s += g_group_loss[idx];
    sm[t] = s;
    __syncthreads();
    for (int w = 128; w > 0; w >>= 1) {
        if (t < w) sm[t] += sm[t + w];
        __syncthreads();
    }
    if (t == 0) out[0] = sm[0] * (1.f / (float)GG);
}

// ---------------------------------------------------------------------------
extern "C" void kernel_launch(void* const* d_in, const int* in_sizes, int n_in,
                              void* d_out, int out_size) {
    const float* x = (const float*)d_in[0];
    dim3 grid1(NN / BN, NN / BM);        // 128 x 128 tiles
    gram_kernel<<<grid1, 256>>>(x);
    group_kernel<<<GG / 8, 256>>>(x);
    reduce_kernel<<<1, 256>>>((float*)d_out);
}

// round 3
// speedup vs baseline: 4.7808x; 4.7808x over previous
#include <cuda_runtime.h>
#include <math.h>
#include <stdint.h>

// Problem constants
#define NN 8192
#define DD 256
#define GG 2048
#define BM 128
#define BN 128
#define BK 32
#define NC (DD / BK)          // 8 K-chunks
#define NTILE (NN / BN)       // 64 column tiles
#define TPAR 0.04f
#define SCALE 36.067376022224085f   // log2(e)/T

__device__ float g_partial[NN * NTILE];   // [row][coltile] masked exp rowsum partials
__device__ float g_group_loss[GG];

// ------------------------------------------------------------------ helpers
__device__ __forceinline__ float ex2f_(float v) {
    float r; asm("ex2.approx.f32 %0, %1;" : "=f"(r) : "f"(v)); return r;
}
__device__ __forceinline__ uint32_t cvt_tf32(float f) {
    uint32_t r; asm("cvt.rna.tf32.f32 %0, %1;" : "=r"(r) : "f"(f)); return r;
}
__device__ __forceinline__ uint32_t smem_u32(const void* p) {
    uint32_t a;
    asm("{ .reg .u64 t; cvta.to.shared.u64 t, %1; cvt.u32.u64 %0, t; }" : "=r"(a) : "l"(p));
    return a;
}
__device__ __forceinline__ void ldsm_x4(uint32_t r[4], uint32_t addr) {
    asm volatile("ldmatrix.sync.aligned.m8n8.x4.shared.b16 {%0,%1,%2,%3}, [%4];"
                 : "=r"(r[0]), "=r"(r[1]), "=r"(r[2]), "=r"(r[3]) : "r"(addr));
}
__device__ __forceinline__ void ldsm_x2(uint32_t r[2], uint32_t addr) {
    asm volatile("ldmatrix.sync.aligned.m8n8.x2.shared.b16 {%0,%1}, [%2];"
                 : "=r"(r[0]), "=r"(r[1]) : "r"(addr));
}
__device__ __forceinline__ void mma_tf32(float c[4], const uint32_t a[4], const uint32_t b[2]) {
    asm volatile(
        "mma.sync.aligned.m16n8k8.row.col.f32.tf32.tf32.f32 "
        "{%0,%1,%2,%3}, {%4,%5,%6,%7}, {%8,%9}, {%0,%1,%2,%3};"
        : "+f"(c[0]), "+f"(c[1]), "+f"(c[2]), "+f"(c[3])
        : "r"(a[0]), "r"(a[1]), "r"(a[2]), "r"(a[3]), "r"(b[0]), "r"(b[1]));
}

// SMEM: per stage A(16KB)+B(16KB); 2 stages = 64KB
#define SA_OFF(s) ((s) * 32768)
#define SB_OFF(s) ((s) * 32768 + 16384)
#define SMEM_BYTES 65536

// ---------------------------------------------------------------------------
// Kernel 1: tf32 mma.sync Gram tile (128x128) + fused exp / mask / rowsum
// ---------------------------------------------------------------------------
__global__ void __launch_bounds__(256, 2) gram_mma(const float* __restrict__ x) {
    extern __shared__ char smem[];
    const uint32_t sb = smem_u32(smem);
    const int tid = threadIdx.x;
    const int lane = tid & 31, wid = tid >> 5;
    const int warp_m = wid & 1;          // 0..1  (64 rows each)
    const int warp_n = wid >> 1;         // 0..3  (32 cols each)
    const int bj = blockIdx.x, bi = blockIdx.y;
    const int R0 = bi * BM, C0 = bj * BN;

    float cc[4][4][4];                   // [mtile][ntile][frag]
    #pragma unroll
    for (int m = 0; m < 4; m++)
        #pragma unroll
        for (int n = 0; n < 4; n++)
            #pragma unroll
            for (int f = 0; f < 4; f++) cc[m][n][f] = 0.f;

    // producer store: row*128 + ((q)^(row&7))*16
    auto ldg_sts = [&](int c, int st) {
        const int kk = c * BK;
        #pragma unroll
        for (int i = 0; i < 4; i++) {
            const int idx = tid + i * 256;
            const int row = idx >> 3;
            const int q   = idx & 7;
            const uint32_t off = (uint32_t)(row * 128 + ((q ^ (row & 7)) << 4));
            float4 a = *reinterpret_cast<const float4*>(x + (size_t)(R0 + row) * DD + kk + q * 4);
            float4 b = *reinterpret_cast<const float4*>(x + (size_t)(C0 + row) * DD + kk + q * 4);
            uint4 at, bt;
            at.x = cvt_tf32(a.x); at.y = cvt_tf32(a.y); at.z = cvt_tf32(a.z); at.w = cvt_tf32(a.w);
            bt.x = cvt_tf32(b.x); bt.y = cvt_tf32(b.y); bt.z = cvt_tf32(b.z); bt.w = cvt_tf32(b.w);
            *reinterpret_cast<uint4*>(smem + SA_OFF(st) + off) = at;
            *reinterpret_cast<uint4*>(smem + SB_OFF(st) + off) = bt;
        }
    };

    // per-lane ldmatrix base addresses
    // A: matrix quad rows; lane 0-15 -> rows (lane&15), lanes 16-31 -> second k-16B chunk
    const int aRow = warp_m * 64 + (lane & 15);
    const int aSel = lane >> 4;              // 0/1: k 16B-chunk parity
    const int aXor = lane & 7;               // (row & 7) since warp_m*64 % 8 == 0
    const uint32_t aBase = sb + (uint32_t)(aRow * 128);
    // B: lanes 0-7 rows n (k-lo), lanes 8-15 same rows (k-hi)
    const int bRow = warp_n * 32 + (lane & 7);
    const int bSel = (lane >> 3) & 1;
    const int bXor = lane & 7;
    const uint32_t bBase = sb + 16384u + (uint32_t)(bRow * 128);

    ldg_sts(0, 0);
    __syncthreads();

    for (int c = 0; c < NC; c++) {
        const int s = c & 1;
        if (c + 1 < NC) ldg_sts(c + 1, s ^ 1);

        const uint32_t sa = aBase + (uint32_t)SA_OFF(s);
        const uint32_t sbb = bBase + (uint32_t)SA_OFF(s);   // bBase already has +16384
        #pragma unroll
        for (int ks = 0; ks < 4; ks++) {
            uint32_t af[4][4], bf[4][2];
            const uint32_t axo = (uint32_t)(((2 * ks + aSel) ^ aXor) << 4);
            const uint32_t bxo = (uint32_t)(((2 * ks + bSel) ^ bXor) << 4);
            #pragma unroll
            for (int m = 0; m < 4; m++) ldsm_x4(af[m], sa + m * 2048u + axo);
            #pragma unroll
            for (int n = 0; n < 4; n++) ldsm_x2(bf[n], sbb + n * 1024u + bxo);
            #pragma unroll
            for (int m = 0; m < 4; m++)
                #pragma unroll
                for (int n = 0; n < 4; n++) mma_tf32(cc[m][n], af[m], bf[n]);
        }
        __syncthreads();
    }

    // Epilogue: exp(s/T), mask in-group columns, per-row partial sums
    // C frag layout: c0,c1 -> row=lane>>2, cols 2(lane&3),+1 ; c2,c3 -> row+8
    float* part = reinterpret_cast<float*>(smem);   // [128][4] = 2KB (stage0 A, now free)
    #pragma unroll
    for (int mt = 0; mt < 4; mt++) {
        const int rl = warp_m * 64 + mt * 16 + (lane >> 2);   // local row (lo half)
        const int r_lo = R0 + rl, r_hi = r_lo + 8;
        float lo = 0.f, hi = 0.f;
        #pragma unroll
        for (int nt = 0; nt < 4; nt++) {
            const int c0 = C0 + warp_n * 32 + nt * 8 + 2 * (lane & 3);
            float e;
            e = ex2f_(cc[mt][nt][0] * SCALE); if ((r_lo >> 2) == (c0 >> 2))       e = 0.f; lo += e;
            e = ex2f_(cc[mt][nt][1] * SCALE); if ((r_lo >> 2) == ((c0 + 1) >> 2)) e = 0.f; lo += e;
            e = ex2f_(cc[mt][nt][2] * SCALE); if ((r_hi >> 2) == (c0 >> 2))       e = 0.f; hi += e;
            e = ex2f_(cc[mt][nt][3] * SCALE); if ((r_hi >> 2) == ((c0 + 1) >> 2)) e = 0.f; hi += e;
        }
        lo += __shfl_xor_sync(0xffffffffu, lo, 1); lo += __shfl_xor_sync(0xffffffffu, lo, 2);
        hi += __shfl_xor_sync(0xffffffffu, hi, 1); hi += __shfl_xor_sync(0xffffffffu, hi, 2);
        if ((lane & 3) == 0) {
            part[rl * 4 + warp_n]       = lo;
            part[(rl + 8) * 4 + warp_n] = hi;
        }
    }
    __syncthreads();
    if (tid < 128) {
        const float s4 = part[tid * 4 + 0] + part[tid * 4 + 1] +
                         part[tid * 4 + 2] + part[tid * 4 + 3];
        g_partial[(size_t)(R0 + tid) * NTILE + bj] = s4;
    }
}

// ---------------------------------------------------------------------------
// Kernel 2: one warp per group (full fp32 positives path) + neg + softplus
// ---------------------------------------------------------------------------
__global__ __launch_bounds__(256) void group_kernel(const float* __restrict__ x) {
    const int warp = threadIdx.x >> 5;
    const int lane = threadIdx.x & 31;
    const int g = blockIdx.x * 8 + warp;

    const int pair = lane & 15;
    const int half = lane >> 4;
    const int i = pair >> 2, j = pair & 3;
    const float* xi = x + (size_t)(4 * g + i) * DD + half * 128;
    const float* xj = x + (size_t)(4 * g + j) * DD + half * 128;
    float dot = 0.f;
    #pragma unroll
    for (int k = 0; k < 128; k += 4) {
        float4 a = *reinterpret_cast<const float4*>(xi + k);
        float4 b = *reinterpret_cast<const float4*>(xj + k);
        dot += a.x * b.x + a.y * b.y + a.z * b.z + a.w * b.w;
    }
    dot += __shfl_down_sync(0xffffffffu, dot, 16);

    float en = ex2f_(-dot * SCALE);
    float rowsum = en;
    rowsum += __shfl_xor_sync(0xffffffffu, rowsum, 1);
    rowsum += __shfl_xor_sync(0xffffffffu, rowsum, 2);
    float inv = 0.25f / rowsum;

    float sum_en = en, sum_inv = inv;
    #pragma unroll
    for (int m = 1; m < 16; m <<= 1) {
        sum_en  += __shfl_xor_sync(0xffffffffu, sum_en,  m, 16);
        sum_inv += __shfl_xor_sync(0xffffffffu, sum_inv, m, 16);
    }

    // neg: 4 rows x 64 tile-partials = 256 contiguous floats
    float S = 0.f;
    const float* part = g_partial + (size_t)(4 * g) * NTILE;
    #pragma unroll
    for (int t = 0; t < 4 * NTILE; t += 32) S += part[t + lane];
    #pragma unroll
    for (int m = 1; m < 32; m <<= 1) S += __shfl_xor_sync(0xffffffffu, S, m);

    if (lane == 0) {
        float hard_pos  = -TPAR * logf(sum_en);
        float least_pos =  TPAR * logf(sum_inv);
        float neg       =  TPAR * logf(S);
        float alpha = (hard_pos >= 0.f)
            ? (2.f * least_pos * hard_pos / (hard_pos + least_pos)) : 0.f;
        float margin = alpha * hard_pos + (1.f - alpha) * least_pos;
        float z = (neg - margin) / TPAR;
        float sp = (z > 0.f) ? (z + log1pf(expf(-z))) : log1pf(expf(z));
        g_group_loss[g] = sp;
    }
}

// ---------------------------------------------------------------------------
// Kernel 3: deterministic mean
// ---------------------------------------------------------------------------
__global__ void reduce_kernel(float* __restrict__ out) {
    __shared__ float sm[256];
    const int t = threadIdx.x;
    float s = 0.f;
    for (int idx = t; idx < GG; idx += 256) s += g_group_loss[idx];
    sm[t] = s;
    __syncthreads();
    for (int w = 128; w > 0; w >>= 1) {
        if (t < w) sm[t] += sm[t + w];
        __syncthreads();
    }
    if (t == 0) out[0] = sm[0] * (1.f / (float)GG);
}

// ---------------------------------------------------------------------------
extern "C" void kernel_launch(void* const* d_in, const int* in_sizes, int n_in,
                              void* d_out, int out_size) {
    const float* x = (const float*)d_in[0];
    static int configured = 0;
    if (!configured) {
        cudaFuncSetAttribute(gram_mma, cudaFuncAttributeMaxDynamicSharedMemorySize, SMEM_BYTES);
        configured = 1;
    }
    dim3 grid1(NTILE, NN / BM);   // 64 x 64 tiles
    gram_mma<<<grid1, 256, SMEM_BYTES>>>(x);
    group_kernel<<<GG / 8, 256>>>(x);
    reduce_kernel<<<1, 256>>>((float*)d_out);
}

// round 4
// speedup vs baseline: 8.2504x; 1.7257x over previous
#include <cuda_runtime.h>
#include <math.h>
#include <stdint.h>

// Problem constants
#define NN 8192
#define DD 256
#define GG 2048
#define BM 128
#define BN 128
#define BK 32
#define NC (DD / BK)          // 8 K-chunks
#define NTILE (NN / BN)       // 64 column tiles
#define NPAIR (NTILE * (NTILE + 1) / 2)   // 2080 upper-tri tiles
#define TPAR 0.04f
#define SCALE 36.067376022224085f   // log2(e)/T

__device__ float g_partial[NN * NTILE];   // [row][coltile] masked exp rowsum partials
__device__ float g_group_loss[GG];

// ------------------------------------------------------------------ helpers
__device__ __forceinline__ float ex2f_(float v) {
    float r; asm("ex2.approx.f32 %0, %1;" : "=f"(r) : "f"(v)); return r;
}
__device__ __forceinline__ uint32_t cvt_tf32(float f) {
    uint32_t r; asm("cvt.rna.tf32.f32 %0, %1;" : "=r"(r) : "f"(f)); return r;
}
__device__ __forceinline__ uint32_t smem_u32(const void* p) {
    uint32_t a;
    asm("{ .reg .u64 t; cvta.to.shared.u64 t, %1; cvt.u32.u64 %0, t; }" : "=r"(a) : "l"(p));
    return a;
}
__device__ __forceinline__ void ldsm_x4(uint32_t r[4], uint32_t addr) {
    asm volatile("ldmatrix.sync.aligned.m8n8.x4.shared.b16 {%0,%1,%2,%3}, [%4];"
                 : "=r"(r[0]), "=r"(r[1]), "=r"(r[2]), "=r"(r[3]) : "r"(addr));
}
__device__ __forceinline__ void ldsm_x2(uint32_t r[2], uint32_t addr) {
    asm volatile("ldmatrix.sync.aligned.m8n8.x2.shared.b16 {%0,%1}, [%2];"
                 : "=r"(r[0]), "=r"(r[1]) : "r"(addr));
}
__device__ __forceinline__ void mma_tf32(float c[4], const uint32_t a[4], const uint32_t b[2]) {
    asm volatile(
        "mma.sync.aligned.m16n8k8.row.col.f32.tf32.tf32.f32 "
        "{%0,%1,%2,%3}, {%4,%5,%6,%7}, {%8,%9}, {%0,%1,%2,%3};"
        : "+f"(c[0]), "+f"(c[1]), "+f"(c[2]), "+f"(c[3])
        : "r"(a[0]), "r"(a[1]), "r"(a[2]), "r"(a[3]), "r"(b[0]), "r"(b[1]));
}

// SMEM: per stage A(16KB)+B(16KB); 2 stages = 64KB
#define SA_OFF(s) ((s) * 32768)
#define SB_OFF(s) ((s) * 32768 + 16384)
#define SMEM_BYTES 65536

// ---------------------------------------------------------------------------
// Kernel 1: tf32 mma.sync Gram, upper-triangular tiles only (symmetry).
// Off-diagonal tiles emit BOTH row-sum partials (rows R0..) and col-sum
// partials (rows C0..). Diagonal tiles mask in-group entries, row-sums only.
// ---------------------------------------------------------------------------
__global__ void __launch_bounds__(256, 2) gram_mma(const float* __restrict__ x) {
    extern __shared__ char smem[];
    const uint32_t sb = smem_u32(smem);
    const int tid = threadIdx.x;
    const int lane = tid & 31, wid = tid >> 5;
    const int warp_m = wid & 1;          // 0..1  (64 rows each)
    const int warp_n = wid >> 1;         // 0..3  (32 cols each)

    // linear bid -> upper-tri (bi <= bj). C(i) = 64i - i(i-1)/2 tiles before row i.
    const int bid = blockIdx.x;
    int bi = (int)((129.0f - sqrtf(16641.0f - 8.0f * (float)bid)) * 0.5f);
    if (bi > 63) bi = 63;
    // integer correction (float sqrt is inexact)
    while (bi > 0 && (NTILE * bi - (bi * (bi - 1)) / 2) > bid) bi--;
    while ((NTILE * (bi + 1) - ((bi + 1) * bi) / 2) <= bid) bi++;
    const int bj = bi + (bid - (NTILE * bi - (bi * (bi - 1)) / 2));
    const int R0 = bi * BM, C0 = bj * BN;
    const bool diag = (bi == bj);

    float cc[4][4][4];                   // [mtile][ntile][frag]
    #pragma unroll
    for (int m = 0; m < 4; m++)
        #pragma unroll
        for (int n = 0; n < 4; n++)
            #pragma unroll
            for (int f = 0; f < 4; f++) cc[m][n][f] = 0.f;

    auto ldg_sts = [&](int c, int st) {
        const int kk = c * BK;
        #pragma unroll
        for (int i = 0; i < 4; i++) {
            const int idx = tid + i * 256;
            const int row = idx >> 3;
            const int q   = idx & 7;
            const uint32_t off = (uint32_t)(row * 128 + ((q ^ (row & 7)) << 4));
            float4 a = *reinterpret_cast<const float4*>(x + (size_t)(R0 + row) * DD + kk + q * 4);
            float4 b = *reinterpret_cast<const float4*>(x + (size_t)(C0 + row) * DD + kk + q * 4);
            uint4 at, bt;
            at.x = cvt_tf32(a.x); at.y = cvt_tf32(a.y); at.z = cvt_tf32(a.z); at.w = cvt_tf32(a.w);
            bt.x = cvt_tf32(b.x); bt.y = cvt_tf32(b.y); bt.z = cvt_tf32(b.z); bt.w = cvt_tf32(b.w);
            *reinterpret_cast<uint4*>(smem + SA_OFF(st) + off) = at;
            *reinterpret_cast<uint4*>(smem + SB_OFF(st) + off) = bt;
        }
    };

    const int aRow = warp_m * 64 + (lane & 15);
    const int aSel = lane >> 4;
    const int aXor = lane & 7;
    const uint32_t aBase = sb + (uint32_t)(aRow * 128);
    const int bRow = warp_n * 32 + (lane & 7);
    const int bSel = (lane >> 3) & 1;
    const int bXor = lane & 7;
    const uint32_t bBase = sb + 16384u + (uint32_t)(bRow * 128);

    ldg_sts(0, 0);
    __syncthreads();

    for (int c = 0; c < NC; c++) {
        const int s = c & 1;
        if (c + 1 < NC) ldg_sts(c + 1, s ^ 1);

        const uint32_t sa  = aBase + (uint32_t)SA_OFF(s);
        const uint32_t sbb = bBase + (uint32_t)SA_OFF(s);
        #pragma unroll
        for (int ks = 0; ks < 4; ks++) {
            uint32_t af[4][4], bf[4][2];
            const uint32_t axo = (uint32_t)(((2 * ks + aSel) ^ aXor) << 4);
            const uint32_t bxo = (uint32_t)(((2 * ks + bSel) ^ bXor) << 4);
            #pragma unroll
            for (int m = 0; m < 4; m++) ldsm_x4(af[m], sa + m * 2048u + axo);
            #pragma unroll
            for (int n = 0; n < 4; n++) ldsm_x2(bf[n], sbb + n * 1024u + bxo);
            #pragma unroll
            for (int m = 0; m < 4; m++)
                #pragma unroll
                for (int n = 0; n < 4; n++) mma_tf32(cc[m][n], af[m], bf[n]);
        }
        __syncthreads();
    }

    // Epilogue. smem reuse: rowpart[128][4] at 0 (2KB), colpart[128][2] at 2048 (1KB)
    float* rowpart = reinterpret_cast<float*>(smem);
    float* colpart = reinterpret_cast<float*>(smem + 2048);

    if (diag) {
        #pragma unroll
        for (int mt = 0; mt < 4; mt++) {
            const int rl = warp_m * 64 + mt * 16 + (lane >> 2);
            const int r_lo = R0 + rl, r_hi = r_lo + 8;
            float lo = 0.f, hi = 0.f;
            #pragma unroll
            for (int nt = 0; nt < 4; nt++) {
                const int c0 = C0 + warp_n * 32 + nt * 8 + 2 * (lane & 3);
                float e;
                e = ex2f_(cc[mt][nt][0] * SCALE); if ((r_lo >> 2) == (c0 >> 2))       e = 0.f; lo += e;
                e = ex2f_(cc[mt][nt][1] * SCALE); if ((r_lo >> 2) == ((c0 + 1) >> 2)) e = 0.f; lo += e;
                e = ex2f_(cc[mt][nt][2] * SCALE); if ((r_hi >> 2) == (c0 >> 2))       e = 0.f; hi += e;
                e = ex2f_(cc[mt][nt][3] * SCALE); if ((r_hi >> 2) == ((c0 + 1) >> 2)) e = 0.f; hi += e;
            }
            lo += __shfl_xor_sync(0xffffffffu, lo, 1); lo += __shfl_xor_sync(0xffffffffu, lo, 2);
            hi += __shfl_xor_sync(0xffffffffu, hi, 1); hi += __shfl_xor_sync(0xffffffffu, hi, 2);
            if ((lane & 3) == 0) {
                rowpart[rl * 4 + warp_n]       = lo;
                rowpart[(rl + 8) * 4 + warp_n] = hi;
            }
        }
    } else {
        float colacc[4][2];
        #pragma unroll
        for (int nt = 0; nt < 4; nt++) { colacc[nt][0] = 0.f; colacc[nt][1] = 0.f; }
        #pragma unroll
        for (int mt = 0; mt < 4; mt++) {
            const int rl = warp_m * 64 + mt * 16 + (lane >> 2);
            float lo = 0.f, hi = 0.f;
            #pragma unroll
            for (int nt = 0; nt < 4; nt++) {
                float e0 = ex2f_(cc[mt][nt][0] * SCALE);
                float e1 = ex2f_(cc[mt][nt][1] * SCALE);
                float e2 = ex2f_(cc[mt][nt][2] * SCALE);
                float e3 = ex2f_(cc[mt][nt][3] * SCALE);
                lo += e0 + e1;  hi += e2 + e3;
                colacc[nt][0] += e0 + e2;
                colacc[nt][1] += e1 + e3;
            }
            lo += __shfl_xor_sync(0xffffffffu, lo, 1); lo += __shfl_xor_sync(0xffffffffu, lo, 2);
            hi += __shfl_xor_sync(0xffffffffu, hi, 1); hi += __shfl_xor_sync(0xffffffffu, hi, 2);
            if ((lane & 3) == 0) {
                rowpart[rl * 4 + warp_n]       = lo;
                rowpart[(rl + 8) * 4 + warp_n] = hi;
            }
        }
        // reduce column partials across the 8 row-lane groups (lane>>2)
        #pragma unroll
        for (int nt = 0; nt < 4; nt++) {
            #pragma unroll
            for (int p = 0; p < 2; p++) {
                float v = colacc[nt][p];
                v += __shfl_xor_sync(0xffffffffu, v, 4);
                v += __shfl_xor_sync(0xffffffffu, v, 8);
                v += __shfl_xor_sync(0xffffffffu, v, 16);
                colacc[nt][p] = v;
            }
        }
        if (lane < 4) {
            #pragma unroll
            for (int nt = 0; nt < 4; nt++) {
                const int cl = warp_n * 32 + nt * 8 + 2 * lane;
                colpart[cl * 2 + warp_m]       = colacc[nt][0];
                colpart[(cl + 1) * 2 + warp_m] = colacc[nt][1];
            }
        }
    }
    __syncthreads();
    if (tid < 128) {
        const float s4 = rowpart[tid * 4 + 0] + rowpart[tid * 4 + 1] +
                         rowpart[tid * 4 + 2] + rowpart[tid * 4 + 3];
        g_partial[(size_t)(R0 + tid) * NTILE + bj] = s4;
        if (!diag) {
            const float s2 = colpart[tid * 2 + 0] + colpart[tid * 2 + 1];
            g_partial[(size_t)(C0 + tid) * NTILE + bi] = s2;
        }
    }
}

// ---------------------------------------------------------------------------
// Kernel 2: one warp per group (full fp32 positives path) + neg + softplus
// ---------------------------------------------------------------------------
__global__ __launch_bounds__(256) void group_kernel(const float* __restrict__ x) {
    const int warp = threadIdx.x >> 5;
    const int lane = threadIdx.x & 31;
    const int g = blockIdx.x * 8 + warp;

    const int pair = lane & 15;
    const int half = lane >> 4;
    const int i = pair >> 2, j = pair & 3;
    const float* xi = x + (size_t)(4 * g + i) * DD + half * 128;
    const float* xj = x + (size_t)(4 * g + j) * DD + half * 128;
    float dot = 0.f;
    #pragma unroll
    for (int k = 0; k < 128; k += 4) {
        float4 a = *reinterpret_cast<const float4*>(xi + k);
        float4 b = *reinterpret_cast<const float4*>(xj + k);
        dot += a.x * b.x + a.y * b.y + a.z * b.z + a.w * b.w;
    }
    dot += __shfl_down_sync(0xffffffffu, dot, 16);

    float en = ex2f_(-dot * SCALE);
    float rowsum = en;
    rowsum += __shfl_xor_sync(0xffffffffu, rowsum, 1);
    rowsum += __shfl_xor_sync(0xffffffffu, rowsum, 2);
    float inv = 0.25f / rowsum;

    float sum_en = en, sum_inv = inv;
    #pragma unroll
    for (int m = 1; m < 16; m <<= 1) {
        sum_en  += __shfl_xor_sync(0xffffffffu, sum_en,  m, 16);
        sum_inv += __shfl_xor_sync(0xffffffffu, sum_inv, m, 16);
    }

    float S = 0.f;
    const float* part = g_partial + (size_t)(4 * g) * NTILE;
    #pragma unroll
    for (int t = 0; t < 4 * NTILE; t += 32) S += part[t + lane];
    #pragma unroll
    for (int m = 1; m < 32; m <<= 1) S += __shfl_xor_sync(0xffffffffu, S, m);

    if (lane == 0) {
        float hard_pos  = -TPAR * logf(sum_en);
        float least_pos =  TPAR * logf(sum_inv);
        float neg       =  TPAR * logf(S);
        float alpha = (hard_pos >= 0.f)
            ? (2.f * least_pos * hard_pos / (hard_pos + least_pos)) : 0.f;
        float margin = alpha * hard_pos + (1.f - alpha) * least_pos;
        float z = (neg - margin) / TPAR;
        float sp = (z > 0.f) ? (z + log1pf(expf(-z))) : log1pf(expf(z));
        g_group_loss[g] = sp;
    }
}

// ---------------------------------------------------------------------------
// Kernel 3: deterministic mean
// ---------------------------------------------------------------------------
__global__ void reduce_kernel(float* __restrict__ out) {
    __shared__ float sm[256];
    const int t = threadIdx.x;
    float s = 0.f;
    for (int idx = t; idx < GG; idx += 256) s += g_group_loss[idx];
    sm[t] = s;
    __syncthreads();
    for (int w = 128; w > 0; w >>= 1) {
        if (t < w) sm[t] += sm[t + w];
        __syncthreads();
    }
    if (t == 0) out[0] = sm[0] * (1.f / (float)GG);
}

// ---------------------------------------------------------------------------
extern "C" void kernel_launch(void* const* d_in, const int* in_sizes, int n_in,
                              void* d_out, int out_size) {
    const float* x = (const float*)d_in[0];
    static int configured = 0;
    if (!configured) {
        cudaFuncSetAttribute(gram_mma, cudaFuncAttributeMaxDynamicSharedMemorySize, SMEM_BYTES);
        configured = 1;
    }
    gram_mma<<<NPAIR, 256, SMEM_BYTES>>>(x);
    group_kernel<<<GG / 8, 256>>>(x);
    reduce_kernel<<<1, 256>>>((float*)d_out);
}